// round 11
// baseline (speedup 1.0000x reference)
#include <cuda_runtime.h>
#include <cuda_fp16.h>

#define N_NODES 50000
#define N_EDGES 800000
#define D 128

#define SCAN_B 512
#define SCAN_BLOCKS ((N_NODES + SCAN_B - 1) / SCAN_B)   // 98

#define TM 128                                            // GEMM rows per block
#define GEMM_BLOCKS ((N_NODES + TM - 1) / TM)             // 391
#define PERM_EPT 4
#define PERM_BLOCKS ((N_EDGES + 256 * PERM_EPT - 1) / (256 * PERM_EPT))  // 782
#define HIST_BLOCKS ((N_EDGES / 4 + 255) / 256)           // 782
#define WCONV_BLOCKS 8
#define SPITCH 24   // smem pitch in halves: 48B = 12 banks -> conflict-free frags

// static checks for the 1:2 stripe mapping
static_assert(GEMM_BLOCKS * 3 == GEMM_BLOCKS + PERM_BLOCKS, "stripe ratio");

// Scratch (static __device__ per allocation rules; zero-initialized at load)
__device__ __half g_H[N_NODES * D];       // h = x @ W in fp16  (12.8 MB)
__device__ __half g_WT[D * D];            // W^T in fp16, [n][k]
__device__ int    g_count[N_NODES];       // self-cleaned each invocation
__device__ int    g_start[N_NODES + 1];
__device__ int    g_cursor[N_NODES];
__device__ int    g_bsum[SCAN_BLOCKS];
__device__ int2   g_edge[N_EDGES];        // {val_bits, col} sorted by row

// ---------------------------------------------------------------------------
// Histogram (int4, 4 edges/thread) + W transpose/convert, one launch
// ---------------------------------------------------------------------------
__global__ void hist_wconv_kernel(const int* __restrict__ row,
                                  const float* __restrict__ W) {
    if (blockIdx.x < HIST_BLOCKS) {
        int t = blockIdx.x * blockDim.x + threadIdx.x;
        if (t * 4 >= N_EDGES) return;
        int4 r = __ldg((const int4*)&row[t * 4]);
        atomicAdd(&g_count[r.x], 1);
        atomicAdd(&g_count[r.y], 1);
        atomicAdd(&g_count[r.z], 1);
        atomicAdd(&g_count[r.w], 1);
    } else {
        int b = blockIdx.x - HIST_BLOCKS;
        int base = (b * 256 + threadIdx.x) * 8;
#pragma unroll
        for (int i = 0; i < 8; i++) {
            int idx = base + i;               // linear over g_WT [n*128+k]
            int n = idx >> 7, k = idx & 127;
            g_WT[idx] = __float2half_rn(W[k * D + n]);
        }
    }
}

// ---------------------------------------------------------------------------
// Level 1: per-block sum of 512 counters
// ---------------------------------------------------------------------------
__global__ void scan_reduce_kernel() {
    __shared__ int s[SCAN_B];
    int tid = threadIdx.x;
    int i = blockIdx.x * SCAN_B + tid;
    s[tid] = (i < N_NODES) ? g_count[i] : 0;
    __syncthreads();
#pragma unroll
    for (int off = SCAN_B / 2; off > 0; off >>= 1) {
        if (tid < off) s[tid] += s[tid + off];
        __syncthreads();
    }
    if (tid == 0) g_bsum[blockIdx.x] = s[0];
}

// ---------------------------------------------------------------------------
// Level 2+3 fused scan; self-cleans g_count
// ---------------------------------------------------------------------------
__global__ void scan_apply_kernel() {
    __shared__ int s[SCAN_B];
    __shared__ int sb[128];
    int tid = threadIdx.x;

    if (tid < 128) sb[tid] = (tid < SCAN_BLOCKS) ? g_bsum[tid] : 0;
    __syncthreads();
#pragma unroll
    for (int off = 1; off < 128; off <<= 1) {
        int t = (tid < 128 && tid >= off) ? sb[tid - off] : 0;
        __syncthreads();
        if (tid < 128) sb[tid] += t;
        __syncthreads();
    }
    int boff = (blockIdx.x == 0) ? 0 : sb[blockIdx.x - 1];

    int i = blockIdx.x * SCAN_B + tid;
    int c = (i < N_NODES) ? g_count[i] : 0;
    s[tid] = c;
    __syncthreads();
#pragma unroll
    for (int off = 1; off < SCAN_B; off <<= 1) {
        int t = (tid >= off) ? s[tid - off] : 0;
        __syncthreads();
        s[tid] += t;
        __syncthreads();
    }
    if (i < N_NODES) {
        int ex = boff + s[tid] - c;
        g_start[i] = ex;
        g_cursor[i] = ex;
        g_count[i] = 0;
    }
    if (blockIdx.x == 0 && tid == 0) g_start[N_NODES] = N_EDGES;
}

// ---------------------------------------------------------------------------
// FAT kernel, role STRIPED: bid % 3 == 0 -> GEMM tile (bid/3);
//                           else        -> permute chunk.
// GEMM: fp16 mma m16n8k16, fp32 acc, double-buffered k16 staging (1 sync/iter).
// ---------------------------------------------------------------------------
__global__ void __launch_bounds__(256)
gemm_permute_kernel(const float* __restrict__ X,
                    const int* __restrict__ row,
                    const int* __restrict__ col,
                    const float* __restrict__ vals) {
    __shared__ __half sX[2][TM][SPITCH];    // [buf][m][k16]
    __shared__ __half sW[2][D][SPITCH];     // [buf][n][k16]
    const int tid = threadIdx.x;
    const unsigned bid = blockIdx.x;

    if (bid % 3 == 0) {
        // ------------------------- GEMM tile -------------------------------
        const int gemm_id = bid / 3;
        const int wid  = tid >> 5;
        const int lane = tid & 31;
        const int g    = lane >> 2;
        const int t4   = lane & 3;
        const int block_m = gemm_id * TM;
        const int wrow = wid * 16;

        // staging index precompute
        const int sr = tid >> 2;              // X row 0..127 (with i offset)
        const int skq = (tid & 3) * 4;        // X k quad
        const int wn = tid >> 1;              // W n row
        const int wkk = (tid & 1) * 8;        // W k offset

        float c[16][4];
#pragma unroll
        for (int nt = 0; nt < 16; nt++)
#pragma unroll
            for (int j = 0; j < 4; j++) c[nt][j] = 0.f;

        // stage chunk 0 into buffer 0
        {
            int k0 = 0;
#pragma unroll
            for (int i = 0; i < 2; i++) {
                int r = sr + i * 64;
                int gm = block_m + r;
                float4 xv = make_float4(0.f, 0.f, 0.f, 0.f);
                if (gm < N_NODES) xv = *(const float4*)&X[gm * D + k0 + skq];
                *(__half2*)&sX[0][r][skq]     = __floats2half2_rn(xv.x, xv.y);
                *(__half2*)&sX[0][r][skq + 2] = __floats2half2_rn(xv.z, xv.w);
            }
            uint4 w = *(const uint4*)&g_WT[wn * D + k0 + wkk];
            *(uint4*)&sW[0][wn][wkk] = w;
        }
        __syncthreads();

        for (int kt = 0; kt < 8; kt++) {
            int cur = kt & 1;
            // prefetch next chunk into the other buffer
            if (kt < 7) {
                int k0 = (kt + 1) * 16;
                int nxt = cur ^ 1;
#pragma unroll
                for (int i = 0; i < 2; i++) {
                    int r = sr + i * 64;
                    int gm = block_m + r;
                    float4 xv = make_float4(0.f, 0.f, 0.f, 0.f);
                    if (gm < N_NODES)
                        xv = *(const float4*)&X[gm * D + k0 + skq];
                    *(__half2*)&sX[nxt][r][skq]     = __floats2half2_rn(xv.x, xv.y);
                    *(__half2*)&sX[nxt][r][skq + 2] = __floats2half2_rn(xv.z, xv.w);
                }
                uint4 w = *(const uint4*)&g_WT[wn * D + k0 + wkk];
                *(uint4*)&sW[nxt][wn][wkk] = w;
            }

            unsigned a0 = *(unsigned*)&sX[cur][wrow + g][t4 * 2];
            unsigned a1 = *(unsigned*)&sX[cur][wrow + g + 8][t4 * 2];
            unsigned a2 = *(unsigned*)&sX[cur][wrow + g][t4 * 2 + 8];
            unsigned a3 = *(unsigned*)&sX[cur][wrow + g + 8][t4 * 2 + 8];

#pragma unroll
            for (int nt = 0; nt < 16; nt++) {
                unsigned b0 = *(unsigned*)&sW[cur][nt * 8 + g][t4 * 2];
                unsigned b1 = *(unsigned*)&sW[cur][nt * 8 + g][t4 * 2 + 8];
                asm volatile(
                    "mma.sync.aligned.m16n8k16.row.col.f32.f16.f16.f32 "
                    "{%0,%1,%2,%3}, {%4,%5,%6,%7}, {%8,%9}, {%0,%1,%2,%3};"
                    : "+f"(c[nt][0]), "+f"(c[nt][1]),
                      "+f"(c[nt][2]), "+f"(c[nt][3])
                    : "r"(a0), "r"(a1), "r"(a2), "r"(a3), "r"(b0), "r"(b1));
            }
            __syncthreads();   // next buffer staged AND current reads done
        }

        int r0 = block_m + wrow + g;
        int r1 = r0 + 8;
#pragma unroll
        for (int nt = 0; nt < 16; nt++) {
            int ccol = nt * 8 + t4 * 2;
            if (r0 < N_NODES)
                *(__half2*)&g_H[(size_t)r0 * D + ccol] =
                    __floats2half2_rn(c[nt][0], c[nt][1]);
            if (r1 < N_NODES)
                *(__half2*)&g_H[(size_t)r1 * D + ccol] =
                    __floats2half2_rn(c[nt][2], c[nt][3]);
        }
    } else {
        // ------------------------- permute chunk ---------------------------
        int b = bid - bid / 3 - 1;            // 0..PERM_BLOCKS-1
        int base = b * (256 * PERM_EPT) + tid;
#pragma unroll
        for (int it = 0; it < PERM_EPT; it++) {
            int e = base + it * 256;
            if (e < N_EDGES) {
                int r = row[e];
                int2 pk;
                pk.x = __float_as_int(vals[e]);
                pk.y = col[e];
                int pos = atomicAdd(&g_cursor[r], 1);
                g_edge[pos] = pk;
            }
        }
    }
}

// ---------------------------------------------------------------------------
// Fused CSR SpMM + bias + ReLU: one warp per output row.
// 16 lanes per edge, uint4 (8 halves) per lane, two edges per step.
// ---------------------------------------------------------------------------
__global__ void spmm_kernel(const float* __restrict__ bias,
                            float* __restrict__ out) {
    int warp = (blockIdx.x * blockDim.x + threadIdx.x) >> 5;
    if (warp >= N_NODES) return;
    int lane = threadIdx.x & 31;
    int half = lane >> 4;
    int sub  = lane & 15;

    int p   = g_start[warp];
    int end = g_start[warp + 1];

    float acc[8];
#pragma unroll
    for (int j = 0; j < 8; j++) acc[j] = 0.f;

    for (; p < end; p += 8) {
        int2  e[4];
        uint4 h[4];
        float v[4];
#pragma unroll
        for (int u = 0; u < 4; u++) {
            int idx = p + u * 2 + half;
            int idxc = (idx < end) ? idx : p;
            e[u] = __ldg(&g_edge[idxc]);
            v[u] = (idx < end) ? __int_as_float(e[u].x) : 0.f;
        }
#pragma unroll
        for (int u = 0; u < 4; u++)
            h[u] = __ldg((const uint4*)&g_H[(size_t)e[u].y * D + sub * 8]);
#pragma unroll
        for (int u = 0; u < 4; u++) {
            float2 f0 = __half22float2(*(__half2*)&h[u].x);
            float2 f1 = __half22float2(*(__half2*)&h[u].y);
            float2 f2 = __half22float2(*(__half2*)&h[u].z);
            float2 f3 = __half22float2(*(__half2*)&h[u].w);
            acc[0] += v[u] * f0.x; acc[1] += v[u] * f0.y;
            acc[2] += v[u] * f1.x; acc[3] += v[u] * f1.y;
            acc[4] += v[u] * f2.x; acc[5] += v[u] * f2.y;
            acc[6] += v[u] * f3.x; acc[7] += v[u] * f3.y;
        }
    }

#pragma unroll
    for (int j = 0; j < 8; j++)
        acc[j] += __shfl_xor_sync(0xffffffffu, acc[j], 16);

    if (half == 0) {
        float4 b0 = *(const float4*)&bias[sub * 8];
        float4 b1 = *(const float4*)&bias[sub * 8 + 4];
        float4 r0, r1;
        r0.x = fmaxf(acc[0] + b0.x, 0.f);
        r0.y = fmaxf(acc[1] + b0.y, 0.f);
        r0.z = fmaxf(acc[2] + b0.z, 0.f);
        r0.w = fmaxf(acc[3] + b0.w, 0.f);
        r1.x = fmaxf(acc[4] + b1.x, 0.f);
        r1.y = fmaxf(acc[5] + b1.y, 0.f);
        r1.z = fmaxf(acc[6] + b1.z, 0.f);
        r1.w = fmaxf(acc[7] + b1.w, 0.f);
        *(float4*)&out[(size_t)warp * D + sub * 8]     = r0;
        *(float4*)&out[(size_t)warp * D + sub * 8 + 4] = r1;
    }
}

// ---------------------------------------------------------------------------
// Launch
// ---------------------------------------------------------------------------
extern "C" void kernel_launch(void* const* d_in, const int* in_sizes, int n_in,
                              void* d_out, int out_size) {
    const float* x      = (const float*)d_in[0];   // [50000,128]
    const float* weight = (const float*)d_in[1];   // [128,128]
    const float* bias   = (const float*)d_in[2];   // [128]
    const float* vals   = (const float*)d_in[3];   // [800000]
    const int*   row    = (const int*)d_in[4];     // [800000]
    const int*   col    = (const int*)d_in[5];     // [800000]
    float* out = (float*)d_out;                    // [50000,128]

    // 1) histogram + W transpose/convert, then 2-step scan
    hist_wconv_kernel<<<HIST_BLOCKS + WCONV_BLOCKS, 256>>>(row, weight);
    scan_reduce_kernel<<<SCAN_BLOCKS, SCAN_B>>>();
    scan_apply_kernel<<<SCAN_BLOCKS, SCAN_B>>>();

    // 2) tensor-core GEMM + edge permute, STRIPED for true co-residency
    gemm_permute_kernel<<<GEMM_BLOCKS + PERM_BLOCKS, 256>>>(x, row, col, vals);

    // 3) fused SpMM + bias + ReLU
    spmm_kernel<<<(N_NODES + 7) / 8, 256>>>(bias, out);
}

// round 12
// speedup vs baseline: 1.0900x; 1.0900x over previous
#include <cuda_runtime.h>
#include <cuda_fp16.h>

#define N_NODES 50000
#define N_EDGES 800000
#define D 128

#define SCAN_B 512
#define SCAN_BLOCKS ((N_NODES + SCAN_B - 1) / SCAN_B)   // 98

#define TM 128                                            // GEMM rows per block
#define GEMM_BLOCKS ((N_NODES + TM - 1) / TM)             // 391
#define PERM_EPT 4
#define PERM_BLOCKS ((N_EDGES + 256 * PERM_EPT - 1) / (256 * PERM_EPT))  // 782
#define HIST_BLOCKS ((N_EDGES / 4 + 255) / 256)           // 782
#define WCONV_BLOCKS 8
#define WPITCH 136   // halves; bank = (4g + t4 + 8kt) mod 32 -> conflict-free

// Scratch (static __device__ per allocation rules; zero-initialized at load)
__device__ __half g_H[N_NODES * D];       // h = x @ W in fp16  (12.8 MB)
__device__ __half g_WT[D * D];            // W^T in fp16, [n][k]
__device__ int    g_count[N_NODES];       // self-cleaned each invocation
__device__ int    g_start[N_NODES + 1];
__device__ int    g_cursor[N_NODES];
__device__ int    g_bsum[SCAN_BLOCKS];
__device__ int2   g_edge[N_EDGES];        // {val_bits, col} sorted by row

// ---------------------------------------------------------------------------
// Histogram (int4, 4 edges/thread) + W transpose/convert, one launch
// ---------------------------------------------------------------------------
__global__ void hist_wconv_kernel(const int* __restrict__ row,
                                  const float* __restrict__ W) {
    if (blockIdx.x < HIST_BLOCKS) {
        int t = blockIdx.x * blockDim.x + threadIdx.x;
        if (t * 4 >= N_EDGES) return;
        int4 r = __ldg((const int4*)&row[t * 4]);
        atomicAdd(&g_count[r.x], 1);
        atomicAdd(&g_count[r.y], 1);
        atomicAdd(&g_count[r.z], 1);
        atomicAdd(&g_count[r.w], 1);
    } else {
        int b = blockIdx.x - HIST_BLOCKS;
        int base = (b * 256 + threadIdx.x) * 8;
#pragma unroll
        for (int i = 0; i < 8; i++) {
            int idx = base + i;               // linear over g_WT [n*128+k]
            int n = idx >> 7, k = idx & 127;
            g_WT[idx] = __float2half_rn(W[k * D + n]);
        }
    }
}

// ---------------------------------------------------------------------------
// Level 1: per-block sum of 512 counters
// ---------------------------------------------------------------------------
__global__ void scan_reduce_kernel() {
    __shared__ int s[SCAN_B];
    int tid = threadIdx.x;
    int i = blockIdx.x * SCAN_B + tid;
    s[tid] = (i < N_NODES) ? g_count[i] : 0;
    __syncthreads();
#pragma unroll
    for (int off = SCAN_B / 2; off > 0; off >>= 1) {
        if (tid < off) s[tid] += s[tid + off];
        __syncthreads();
    }
    if (tid == 0) g_bsum[blockIdx.x] = s[0];
}

// ---------------------------------------------------------------------------
// Level 2+3 fused scan; self-cleans g_count
// ---------------------------------------------------------------------------
__global__ void scan_apply_kernel() {
    __shared__ int s[SCAN_B];
    __shared__ int sb[128];
    int tid = threadIdx.x;

    if (tid < 128) sb[tid] = (tid < SCAN_BLOCKS) ? g_bsum[tid] : 0;
    __syncthreads();
#pragma unroll
    for (int off = 1; off < 128; off <<= 1) {
        int t = (tid < 128 && tid >= off) ? sb[tid - off] : 0;
        __syncthreads();
        if (tid < 128) sb[tid] += t;
        __syncthreads();
    }
    int boff = (blockIdx.x == 0) ? 0 : sb[blockIdx.x - 1];

    int i = blockIdx.x * SCAN_B + tid;
    int c = (i < N_NODES) ? g_count[i] : 0;
    s[tid] = c;
    __syncthreads();
#pragma unroll
    for (int off = 1; off < SCAN_B; off <<= 1) {
        int t = (tid >= off) ? s[tid - off] : 0;
        __syncthreads();
        s[tid] += t;
        __syncthreads();
    }
    if (i < N_NODES) {
        int ex = boff + s[tid] - c;
        g_start[i] = ex;
        g_cursor[i] = ex;
        g_count[i] = 0;
    }
    if (blockIdx.x == 0 && tid == 0) g_start[N_NODES] = N_EDGES;
}

// ---------------------------------------------------------------------------
// FAT kernel (sequential roles): blocks [0, GEMM_BLOCKS): tensor GEMM;
//                                rest: edge permute.
// GEMM: W^T staged ONCE (1 sync), A-fragments loaded directly from global X
// (fp32 -> fp16 in regs), mainloop has NO barriers.
// ---------------------------------------------------------------------------
__global__ void __launch_bounds__(256)
gemm_permute_kernel(const float* __restrict__ X,
                    const int* __restrict__ row,
                    const int* __restrict__ col,
                    const float* __restrict__ vals) {
    __shared__ __half sW[D][WPITCH];      // W^T whole: [n][k]
    const int tid = threadIdx.x;

    if (blockIdx.x < GEMM_BLOCKS) {
        const int wid  = tid >> 5;
        const int lane = tid & 31;
        const int g    = lane >> 2;       // 0..7
        const int t4   = lane & 3;        // 0..3
        const int block_m = blockIdx.x * TM;
        const int wrow = wid * 16;

        // stage full W^T (16384 halves = 2048 uint4) once
#pragma unroll
        for (int i = 0; i < 8; i++) {
            int u = tid + i * 256;            // uint4 index
            int n = u >> 4;                   // 16 uint4 per 128-half row
            int kk = (u & 15) * 8;
            uint4 w = *(const uint4*)&g_WT[n * D + kk];
            *(uint4*)&sW[n][kk] = w;
        }
        __syncthreads();                      // the ONLY barrier

        int r0 = block_m + wrow + g;
        int r1 = r0 + 8;
        bool p0 = r0 < N_NODES;
        bool p1 = r1 < N_NODES;
        const float* x0 = X + (size_t)(p0 ? r0 : 0) * D;
        const float* x1 = X + (size_t)(p1 ? r1 : 0) * D;

        float c[16][4];
#pragma unroll
        for (int nt = 0; nt < 16; nt++)
#pragma unroll
            for (int j = 0; j < 4; j++) c[nt][j] = 0.f;

#pragma unroll
        for (int kt = 0; kt < 8; kt++) {
            int kb = kt * 16 + t4 * 2;
            float2 f00 = *(const float2*)&x0[kb];       // row g,  k<8 half
            float2 f01 = *(const float2*)&x0[kb + 8];   // row g,  k>=8 half
            float2 f10 = *(const float2*)&x1[kb];       // row g+8
            float2 f11 = *(const float2*)&x1[kb + 8];
            __half2 ha0 = __floats2half2_rn(f00.x, f00.y);
            __half2 ha1 = __floats2half2_rn(f10.x, f10.y);
            __half2 ha2 = __floats2half2_rn(f01.x, f01.y);
            __half2 ha3 = __floats2half2_rn(f11.x, f11.y);
            unsigned a0 = *(unsigned*)&ha0;
            unsigned a1 = *(unsigned*)&ha1;
            unsigned a2 = *(unsigned*)&ha2;
            unsigned a3 = *(unsigned*)&ha3;

#pragma unroll
            for (int nt = 0; nt < 16; nt++) {
                unsigned b0 = *(unsigned*)&sW[nt * 8 + g][kt * 16 + t4 * 2];
                unsigned b1 = *(unsigned*)&sW[nt * 8 + g][kt * 16 + 8 + t4 * 2];
                asm volatile(
                    "mma.sync.aligned.m16n8k16.row.col.f32.f16.f16.f32 "
                    "{%0,%1,%2,%3}, {%4,%5,%6,%7}, {%8,%9}, {%0,%1,%2,%3};"
                    : "+f"(c[nt][0]), "+f"(c[nt][1]),
                      "+f"(c[nt][2]), "+f"(c[nt][3])
                    : "r"(a0), "r"(a1), "r"(a2), "r"(a3), "r"(b0), "r"(b1));
            }
        }

#pragma unroll
        for (int nt = 0; nt < 16; nt++) {
            int ccol = nt * 8 + t4 * 2;
            if (p0)
                *(__half2*)&g_H[(size_t)r0 * D + ccol] =
                    __floats2half2_rn(c[nt][0], c[nt][1]);
            if (p1)
                *(__half2*)&g_H[(size_t)r1 * D + ccol] =
                    __floats2half2_rn(c[nt][2], c[nt][3]);
        }
    } else {
        int b = blockIdx.x - GEMM_BLOCKS;
        int base = b * (256 * PERM_EPT) + tid;
#pragma unroll
        for (int it = 0; it < PERM_EPT; it++) {
            int e = base + it * 256;
            if (e < N_EDGES) {
                int r = row[e];
                int2 pk;
                pk.x = __float_as_int(vals[e]);
                pk.y = col[e];
                int pos = atomicAdd(&g_cursor[r], 1);
                g_edge[pos] = pk;
            }
        }
    }
}

// ---------------------------------------------------------------------------
// Fused CSR SpMM + bias + ReLU: one warp per output row.
// 16 lanes per edge, uint4 (8 halves) per lane, two edges per step.
// ---------------------------------------------------------------------------
__global__ void spmm_kernel(const float* __restrict__ bias,
                            float* __restrict__ out) {
    int warp = (blockIdx.x * blockDim.x + threadIdx.x) >> 5;
    if (warp >= N_NODES) return;
    int lane = threadIdx.x & 31;
    int half = lane >> 4;
    int sub  = lane & 15;

    int p   = g_start[warp];
    int end = g_start[warp + 1];

    float acc[8];
#pragma unroll
    for (int j = 0; j < 8; j++) acc[j] = 0.f;

    for (; p < end; p += 8) {
        int2  e[4];
        uint4 h[4];
        float v[4];
#pragma unroll
        for (int u = 0; u < 4; u++) {
            int idx = p + u * 2 + half;
            int idxc = (idx < end) ? idx : p;
            e[u] = __ldg(&g_edge[idxc]);
            v[u] = (idx < end) ? __int_as_float(e[u].x) : 0.f;
        }
#pragma unroll
        for (int u = 0; u < 4; u++)
            h[u] = __ldg((const uint4*)&g_H[(size_t)e[u].y * D + sub * 8]);
#pragma unroll
        for (int u = 0; u < 4; u++) {
            float2 f0 = __half22float2(*(__half2*)&h[u].x);
            float2 f1 = __half22float2(*(__half2*)&h[u].y);
            float2 f2 = __half22float2(*(__half2*)&h[u].z);
            float2 f3 = __half22float2(*(__half2*)&h[u].w);
            acc[0] += v[u] * f0.x; acc[1] += v[u] * f0.y;
            acc[2] += v[u] * f1.x; acc[3] += v[u] * f1.y;
            acc[4] += v[u] * f2.x; acc[5] += v[u] * f2.y;
            acc[6] += v[u] * f3.x; acc[7] += v[u] * f3.y;
        }
    }

#pragma unroll
    for (int j = 0; j < 8; j++)
        acc[j] += __shfl_xor_sync(0xffffffffu, acc[j], 16);

    if (half == 0) {
        float4 b0 = *(const float4*)&bias[sub * 8];
        float4 b1 = *(const float4*)&bias[sub * 8 + 4];
        float4 r0, r1;
        r0.x = fmaxf(acc[0] + b0.x, 0.f);
        r0.y = fmaxf(acc[1] + b0.y, 0.f);
        r0.z = fmaxf(acc[2] + b0.z, 0.f);
        r0.w = fmaxf(acc[3] + b0.w, 0.f);
        r1.x = fmaxf(acc[4] + b1.x, 0.f);
        r1.y = fmaxf(acc[5] + b1.y, 0.f);
        r1.z = fmaxf(acc[6] + b1.z, 0.f);
        r1.w = fmaxf(acc[7] + b1.w, 0.f);
        *(float4*)&out[(size_t)warp * D + sub * 8]     = r0;
        *(float4*)&out[(size_t)warp * D + sub * 8 + 4] = r1;
    }
}

// ---------------------------------------------------------------------------
// Launch
// ---------------------------------------------------------------------------
extern "C" void kernel_launch(void* const* d_in, const int* in_sizes, int n_in,
                              void* d_out, int out_size) {
    const float* x      = (const float*)d_in[0];   // [50000,128]
    const float* weight = (const float*)d_in[1];   // [128,128]
    const float* bias   = (const float*)d_in[2];   // [128]
    const float* vals   = (const float*)d_in[3];   // [800000]
    const int*   row    = (const int*)d_in[4];     // [800000]
    const int*   col    = (const int*)d_in[5];     // [800000]
    float* out = (float*)d_out;                    // [50000,128]

    // 1) histogram + W transpose/convert, then 2-step scan
    hist_wconv_kernel<<<HIST_BLOCKS + WCONV_BLOCKS, 256>>>(row, weight);
    scan_reduce_kernel<<<SCAN_BLOCKS, SCAN_B>>>();
    scan_apply_kernel<<<SCAN_BLOCKS, SCAN_B>>>();

    // 2) tensor-core GEMM + edge permute (sequential roles, barrier-free GEMM loop)
    gemm_permute_kernel<<<GEMM_BLOCKS + PERM_BLOCKS, 256>>>(x, row, col, vals);

    // 3) fused SpMM + bias + ReLU
    spmm_kernel<<<(N_NODES + 7) / 8, 256>>>(bias, out);
}